// round 10
// baseline (speedup 1.0000x reference)
#include <cuda_runtime.h>
#include <cuda_fp16.h>
#include <cstdint>

#define N_NODES 50000
#define N_EDGES 625000
#define D 128
#define NBLK ((N_NODES + 255) / 256)   // 196 scan blocks
#define XCONV_BLKS (N_NODES * D / 1024) // 6250 (4 floats/thread)
#define M_BLK 128
#define OUT_BLOCKS ((N_NODES + M_BLK - 1) / M_BLK)  // 391
#define SCAN_READY 0x40000000

// ---------------------------------------------------------------------------
// Device scratch (no allocations allowed)
// ---------------------------------------------------------------------------
__device__ int    g_cnt[N_NODES];          // histogram / fill cursor
__device__ int    g_state[NBLK];           // lookback scan: aggregate | READY
__device__ int    g_off[N_NODES + 1];      // CSR row offsets
__device__ int    g_sadj[N_EDGES];         // CSR: src node per in-edge slot
__device__ __half g_xh[N_NODES * D];       // x converted to fp16 (for gather)
__device__ float  g_h[N_NODES * D];        // mean-aggregated neighbor features
__device__ __half g_Whi[D * 256];          // W^T split-hi: [j][k], k in 0..255
__device__ __half g_Wlo[D * 256];          // W^T split-lo

// ---------------------------------------------------------------------------
// 1) fused init (one launch, three independent jobs):
//    blocks [0,NBLK): zero g_cnt + scan states
//    blocks [NBLK, NBLK+128): W -> transposed fp16 hi/lo split
//    blocks [NBLK+128, ...): x -> fp16 (g_xh)
// ---------------------------------------------------------------------------
__global__ void __launch_bounds__(256) init_kernel(
    const float* __restrict__ x,
    const float* __restrict__ Ws, const float* __restrict__ Wn)
{
    int bid = blockIdx.x, t = threadIdx.x;
    if (bid < NBLK) {
        int i = bid * 256 + t;
        if (i < N_NODES) g_cnt[i] = 0;
        if (bid == 0 && t < NBLK) g_state[t] = 0;
    } else if (bid < NBLK + 128) {
        int k = (bid - NBLK) * 2 + (t >> 7);   // 0..255
        int j = t & 127;                       // 0..127
        float w = (k < D) ? Ws[k * D + j] : Wn[(k - D) * D + j];
        __half hi = __float2half_rn(w);
        __half lo = __float2half_rn(w - __half2float(hi));
        g_Whi[j * 256 + k] = hi;
        g_Wlo[j * 256 + k] = lo;
    } else {
        int i = (bid - NBLK - 128) * 256 + t;  // float4 index
        float4 v = reinterpret_cast<const float4*>(x)[i];
        __half2 p0 = __floats2half2_rn(v.x, v.y);
        __half2 p1 = __floats2half2_rn(v.z, v.w);
        uint2 u;
        u.x = *reinterpret_cast<uint32_t*>(&p0);
        u.y = *reinterpret_cast<uint32_t*>(&p1);
        reinterpret_cast<uint2*>(g_xh)[i] = u;
    }
}

// ---------------------------------------------------------------------------
// 2) in-degree histogram
// ---------------------------------------------------------------------------
__global__ void __launch_bounds__(256) hist_kernel(const int* __restrict__ dst) {
    int e = blockIdx.x * blockDim.x + threadIdx.x;
    if (e < N_EDGES) atomicAdd(&g_cnt[dst[e]], 1);
}

// ---------------------------------------------------------------------------
// 3) single-pass scan, aggregate-only decoupled lookback.
//    Safe: block b waits only on aggregates of blocks < b (scheduled earlier;
//    all 196 tiny blocks are co-resident on 148 SMs).
// ---------------------------------------------------------------------------
__global__ void __launch_bounds__(256) scan_kernel() {
    __shared__ int s[256];
    __shared__ int red[256];
    int t = threadIdx.x, bid = blockIdx.x;
    int i = bid * 256 + t;

    int v = (i < N_NODES) ? g_cnt[i] : 0;
    s[t] = v; __syncthreads();
    #pragma unroll
    for (int d = 1; d < 256; d <<= 1) {
        int add = (t >= d) ? s[t - d] : 0;
        __syncthreads();
        s[t] += add; __syncthreads();
    }
    if (t == 0) atomicExch(&g_state[bid], s[255] | SCAN_READY);

    int pref = 0;
    if (t < bid) {
        int st;
        do { st = atomicAdd(&g_state[t], 0); } while (!(st & SCAN_READY));
        pref = st & (SCAN_READY - 1);
    }
    red[t] = pref; __syncthreads();
    #pragma unroll
    for (int sft = 128; sft > 0; sft >>= 1) {
        if (t < sft) red[t] += red[t + sft];
        __syncthreads();
    }
    int prefix = red[0];

    if (i < N_NODES) g_off[i] = (s[t] - v) + prefix;
    if (i == 0)      g_off[N_NODES] = N_EDGES;
}

// ---------------------------------------------------------------------------
// 4) fill CSR (stores src node ids directly); g_cnt returns to 0
// ---------------------------------------------------------------------------
__global__ void __launch_bounds__(256) fill_kernel(
    const int* __restrict__ src, const int* __restrict__ dst)
{
    int e = blockIdx.x * blockDim.x + threadIdx.x;
    if (e >= N_EDGES) return;
    int d = __ldg(&dst[e]);
    int p = atomicSub(&g_cnt[d], 1) - 1;
    g_sadj[g_off[d] + p] = __ldg(&src[e]);
}

// ---------------------------------------------------------------------------
// 5) aggregate from fp16 x: one warp per node.
//    FP16 ROW = 128 halves = 256 BYTES. Lane l owns halves [4l, 4l+4):
//    uint2 (8B) gather per edge -> 32 lanes x 4 halves = exactly 128 cols.
//    fp32 accumulate; float4 store at column 4*lane.
// ---------------------------------------------------------------------------
__global__ void __launch_bounds__(256) agg_kernel() {
    int v    = (blockIdx.x * blockDim.x + threadIdx.x) >> 5;
    int lane = threadIdx.x & 31;
    if (v >= N_NODES) return;

    int beg = g_off[v];
    int end = g_off[v + 1];

    float4 acc = make_float4(0.f, 0.f, 0.f, 0.f);

    int i = beg;
    for (; i + 1 < end; i += 2) {
        int s0 = g_sadj[i];
        int s1 = g_sadj[i + 1];
        uint2 p0 = reinterpret_cast<const uint2*>(g_xh + (size_t)s0 * D)[lane];
        uint2 p1 = reinterpret_cast<const uint2*>(g_xh + (size_t)s1 * D)[lane];
        float2 a = __half22float2(*reinterpret_cast<const __half2*>(&p0.x));
        float2 b = __half22float2(*reinterpret_cast<const __half2*>(&p0.y));
        float2 c = __half22float2(*reinterpret_cast<const __half2*>(&p1.x));
        float2 d = __half22float2(*reinterpret_cast<const __half2*>(&p1.y));
        acc.x += a.x + c.x; acc.y += a.y + c.y;
        acc.z += b.x + d.x; acc.w += b.y + d.y;
    }
    if (i < end) {
        int s0 = g_sadj[i];
        uint2 p0 = reinterpret_cast<const uint2*>(g_xh + (size_t)s0 * D)[lane];
        float2 a = __half22float2(*reinterpret_cast<const __half2*>(&p0.x));
        float2 b = __half22float2(*reinterpret_cast<const __half2*>(&p0.y));
        acc.x += a.x; acc.y += a.y; acc.z += b.x; acc.w += b.y;
    }

    int deg = end - beg;
    float inv = (deg > 0) ? (1.0f / (float)deg) : 0.0f;
    float4 o;
    o.x = acc.x * inv; o.y = acc.y * inv; o.z = acc.z * inv; o.w = acc.w * inv;
    *reinterpret_cast<float4*>(g_h + (size_t)v * D + lane * 4) = o;
}

// ---------------------------------------------------------------------------
// 6) fused tensor-core GEMM: out = [x | h] @ [Ws; Wn] + b
//    fp16 2-term split (AhBh + AlBh + AhBl), fp32 accumulate.
//    128 rows/block, 4 warps x 32 rows, N=128, K=256 in two 128-chunks.
// ---------------------------------------------------------------------------
#define A_STRIDE 264        // 256 + 8 halves pad
#define B_STRIDE 136        // 128 + 8 halves pad
#define SM_A_HI  0
#define SM_A_LO  (M_BLK * A_STRIDE)
#define SM_B_HI  (2 * M_BLK * A_STRIDE)
#define SM_B_LO  (2 * M_BLK * A_STRIDE + D * B_STRIDE)
#define SMEM_HALVES (2 * M_BLK * A_STRIDE + 2 * D * B_STRIDE)  // 102400
#define SMEM_BYTES  (SMEM_HALVES * 2)                           // 204800

__device__ __forceinline__ void ldsm_x4(uint32_t* r, uint32_t addr) {
    asm volatile("ldmatrix.sync.aligned.m8n8.x4.shared.b16 {%0,%1,%2,%3}, [%4];"
                 : "=r"(r[0]), "=r"(r[1]), "=r"(r[2]), "=r"(r[3]) : "r"(addr));
}
__device__ __forceinline__ void mma16816(float* c, const uint32_t* a, const uint32_t* b) {
    asm volatile(
        "mma.sync.aligned.m16n8k16.row.col.f32.f16.f16.f32 "
        "{%0,%1,%2,%3}, {%4,%5,%6,%7}, {%8,%9}, {%0,%1,%2,%3};"
        : "+f"(c[0]), "+f"(c[1]), "+f"(c[2]), "+f"(c[3])
        : "r"(a[0]), "r"(a[1]), "r"(a[2]), "r"(a[3]), "r"(b[0]), "r"(b[1]));
}

__global__ void __launch_bounds__(128, 1) out_kernel(
    const float* __restrict__ x,
    const float* __restrict__ b,
    float*       __restrict__ out)
{
    extern __shared__ __half sm[];
    __half* A_hi = sm + SM_A_HI;
    __half* A_lo = sm + SM_A_LO;
    __half* B_hi = sm + SM_B_HI;
    __half* B_lo = sm + SM_B_LO;

    const int t    = threadIdx.x;
    const int warp = t >> 5;
    const int lane = t & 31;
    const int base = blockIdx.x * M_BLK;

    // ---- stage A: 128 rows of [x | h] fp32 -> fp16 hi/lo ----
    {
        int row_off = t >> 6;          // 0/1
        int part    = (t >> 5) & 1;    // 0: x, 1: h
        int l16     = t & 31;          // float4 index within 128 cols
        const float* srcp = part ? g_h : x;
        #pragma unroll 4
        for (int it = 0; it < 64; it++) {
            int row  = it * 2 + row_off;
            int node = base + row;
            float4 v = make_float4(0.f, 0.f, 0.f, 0.f);
            if (node < N_NODES)
                v = reinterpret_cast<const float4*>(srcp + (size_t)node * D)[l16];
            __half h0 = __float2half_rn(v.x), h1 = __float2half_rn(v.y);
            __half h2 = __float2half_rn(v.z), h3 = __float2half_rn(v.w);
            __half l0 = __float2half_rn(v.x - __half2float(h0));
            __half l1 = __float2half_rn(v.y - __half2float(h1));
            __half l2 = __float2half_rn(v.z - __half2float(h2));
            __half l3 = __float2half_rn(v.w - __half2float(h3));
            int k   = part * 128 + l16 * 4;
            int off = row * A_STRIDE + k;
            __half2 ph0 = __halves2half2(h0, h1), ph1 = __halves2half2(h2, h3);
            __half2 pl0 = __halves2half2(l0, l1), pl1 = __halves2half2(l2, l3);
            uint2 uh, ul;
            uh.x = *reinterpret_cast<uint32_t*>(&ph0);
            uh.y = *reinterpret_cast<uint32_t*>(&ph1);
            ul.x = *reinterpret_cast<uint32_t*>(&pl0);
            ul.y = *reinterpret_cast<uint32_t*>(&pl1);
            *reinterpret_cast<uint2*>(A_hi + off) = uh;
            *reinterpret_cast<uint2*>(A_lo + off) = ul;
        }
    }

    float c[2][16][4];
    #pragma unroll
    for (int mt = 0; mt < 2; mt++)
        #pragma unroll
        for (int nt = 0; nt < 16; nt++)
            #pragma unroll
            for (int i = 0; i < 4; i++) c[mt][nt][i] = 0.f;

    const int mrow = warp * 32;
    const int a_r  = lane & 15;
    const int a_k  = (lane >> 4) * 8;
    const int b_m  = lane >> 3;        // x4 matrix idx 0..3
    const int b_r  = lane & 7;
    const int b_no = (b_m >> 1) * 8;   // n offset 0/8
    const int b_ko = (b_m & 1) * 8;    // k offset 0/8

    for (int kc = 0; kc < 2; kc++) {
        // stage B chunk [128 n][128 k] hi+lo
        __syncthreads();
        {
            int kbase = kc * 128;
            #pragma unroll 4
            for (int idx = t; idx < 128 * 16; idx += 128) {
                int n = idx >> 4, q = idx & 15;
                const uint4* sh = reinterpret_cast<const uint4*>(g_Whi + n * 256 + kbase) + q;
                const uint4* sl = reinterpret_cast<const uint4*>(g_Wlo + n * 256 + kbase) + q;
                *reinterpret_cast<uint4*>(B_hi + n * B_STRIDE + q * 8) = *sh;
                *reinterpret_cast<uint4*>(B_lo + n * B_STRIDE + q * 8) = *sl;
            }
        }
        __syncthreads();

        #pragma unroll
        for (int kt = 0; kt < 8; kt++) {
            int kg = kc * 128 + kt * 16;   // global k for A
            int kk = kt * 16;              // k within B chunk

            uint32_t ah[2][4], al[2][4];
            #pragma unroll
            for (int mt = 0; mt < 2; mt++) {
                int arow = mrow + mt * 16 + a_r;
                ldsm_x4(ah[mt], (uint32_t)__cvta_generic_to_shared(
                    A_hi + arow * A_STRIDE + kg + a_k));
                ldsm_x4(al[mt], (uint32_t)__cvta_generic_to_shared(
                    A_lo + arow * A_STRIDE + kg + a_k));
            }

            #pragma unroll
            for (int np = 0; np < 8; np++) {       // n-tile pairs
                uint32_t bh4[4], bl4[4];
                int nrow = np * 16 + b_no + b_r;
                ldsm_x4(bh4, (uint32_t)__cvta_generic_to_shared(
                    B_hi + nrow * B_STRIDE + kk + b_ko));
                ldsm_x4(bl4, (uint32_t)__cvta_generic_to_shared(
                    B_lo + nrow * B_STRIDE + kk + b_ko));

                #pragma unroll
                for (int ht = 0; ht < 2; ht++) {
                    int nt = np * 2 + ht;
                    const uint32_t* bh = bh4 + ht * 2;
                    const uint32_t* bl = bl4 + ht * 2;
                    #pragma unroll
                    for (int mt = 0; mt < 2; mt++) {
                        mma16816(c[mt][nt], ah[mt], bh);   // AhBh
                        mma16816(c[mt][nt], al[mt], bh);   // AlBh
                        mma16816(c[mt][nt], ah[mt], bl);   // AhBl
                    }
                }
            }
        }
    }

    // ---- epilogue: + bias, store fp32 ----
    #pragma unroll
    for (int nt = 0; nt < 16; nt++) {
        int col = nt * 8 + (lane & 3) * 2;
        float2 bv = *reinterpret_cast<const float2*>(b + col);
        #pragma unroll
        for (int mt = 0; mt < 2; mt++) {
            int r0 = base + mrow + mt * 16 + (lane >> 2);
            int r1 = r0 + 8;
            if (r0 < N_NODES) {
                float2 o; o.x = c[mt][nt][0] + bv.x; o.y = c[mt][nt][1] + bv.y;
                *reinterpret_cast<float2*>(out + (size_t)r0 * D + col) = o;
            }
            if (r1 < N_NODES) {
                float2 o; o.x = c[mt][nt][2] + bv.x; o.y = c[mt][nt][3] + bv.y;
                *reinterpret_cast<float2*>(out + (size_t)r1 * D + col) = o;
            }
        }
    }
}

// ---------------------------------------------------------------------------
// Launch (single stream; stream/event creation is forbidden — it allocates).
// Inputs: x, src, dst, W_self, W_neigh, b
// ---------------------------------------------------------------------------
extern "C" void kernel_launch(void* const* d_in, const int* in_sizes, int n_in,
                              void* d_out, int out_size)
{
    const float* x   = (const float*)d_in[0];
    const int*   src = (const int*)  d_in[1];
    const int*   dst = (const int*)  d_in[2];
    const float* Ws  = (const float*)d_in[3];
    const float* Wn  = (const float*)d_in[4];
    const float* b   = (const float*)d_in[5];
    float*       out = (float*)d_out;

    static bool attr_set = false;
    if (!attr_set) {
        cudaFuncSetAttribute(out_kernel,
                             cudaFuncAttributeMaxDynamicSharedMemorySize, SMEM_BYTES);
        attr_set = true;
    }

    init_kernel<<<NBLK + 128 + XCONV_BLKS, 256>>>(x, Ws, Wn);
    hist_kernel<<<(N_EDGES + 255) / 256, 256>>>(dst);
    scan_kernel<<<NBLK, 256>>>();
    fill_kernel<<<(N_EDGES + 255) / 256, 256>>>(src, dst);
    agg_kernel<<<(N_NODES * 32 + 255) / 256, 256>>>();
    out_kernel<<<OUT_BLOCKS, 128, SMEM_BYTES>>>(x, b, out);
}

// round 11
// speedup vs baseline: 1.1783x; 1.1783x over previous
#include <cuda_runtime.h>
#include <cuda_fp16.h>
#include <cstdint>

#define N_NODES 50000
#define N_EDGES 625000
#define D 128
#define NBLK 196                     // scan blocks (50000/256)
#define EBLK 2442                    // edge blocks (625000/256)
#define M_BLK 128
#define OUT_BLOCKS 391               // ceil(50000/128)
#define SCAN_READY 0x40000000

// ---------------------------------------------------------------------------
// Device scratch. g_cnt invariant: starts 0 (module load), hist adds, fill
// subtracts back to exactly 0 -> no zeroing kernel needed, deterministic.
// ---------------------------------------------------------------------------
__device__ int    g_cnt[N_NODES];
__device__ int    g_state[NBLK];         // lookback scan: aggregate | READY
__device__ int    g_off[N_NODES + 1];    // CSR row offsets
__device__ int    g_sadj[N_EDGES];       // CSR: src node per in-edge slot
__device__ __half g_y[N_NODES * D];      // y = x @ Wn, fp16 (gathered by agg)
__device__ __half g_Whi[256 * D];        // B^T [n][k]: n<128 Ws^T, n>=128 Wn^T (hi)
__device__ __half g_Wlo[256 * D];        // (lo)

// ---------------------------------------------------------------------------
// 1) fused init: blocks [0,EBLK) histogram dst into g_cnt;
//    blocks [EBLK, EBLK+128): W -> [n][k] fp16 hi/lo split (+ g_state clear)
// ---------------------------------------------------------------------------
__global__ void __launch_bounds__(256) init_hist_kernel(
    const int* __restrict__ dst,
    const float* __restrict__ Ws, const float* __restrict__ Wn)
{
    int bid = blockIdx.x, t = threadIdx.x;
    if (bid < EBLK) {
        int e = bid * 256 + t;
        if (e < N_EDGES) atomicAdd(&g_cnt[dst[e]], 1);
    } else {
        int wb = bid - EBLK;                 // 0..127
        if (wb == 0 && t < NBLK) g_state[t] = 0;
        int n = wb * 2 + (t >> 7);           // 0..255 (output col: Ws then Wn)
        int k = t & 127;                     // 0..127 (input dim)
        float w = (n < D) ? Ws[k * D + n] : Wn[k * D + (n - D)];
        __half hi = __float2half_rn(w);
        __half lo = __float2half_rn(w - __half2float(hi));
        g_Whi[n * D + k] = hi;
        g_Wlo[n * D + k] = lo;
    }
}

// ---------------------------------------------------------------------------
// 2) single-pass scan, aggregate-only decoupled lookback (g_cnt -> g_off).
//    Safe: block b waits only on aggregates of blocks < b; all 196 co-resident.
// ---------------------------------------------------------------------------
__global__ void __launch_bounds__(256) scan_kernel() {
    __shared__ int s[256];
    __shared__ int red[256];
    int t = threadIdx.x, bid = blockIdx.x;
    int i = bid * 256 + t;

    int v = (i < N_NODES) ? g_cnt[i] : 0;
    s[t] = v; __syncthreads();
    #pragma unroll
    for (int d = 1; d < 256; d <<= 1) {
        int add = (t >= d) ? s[t - d] : 0;
        __syncthreads();
        s[t] += add; __syncthreads();
    }
    if (t == 0) atomicExch(&g_state[bid], s[255] | SCAN_READY);

    int pref = 0;
    if (t < bid) {
        int st;
        do { st = atomicAdd(&g_state[t], 0); } while (!(st & SCAN_READY));
        pref = st & (SCAN_READY - 1);
    }
    red[t] = pref; __syncthreads();
    #pragma unroll
    for (int sft = 128; sft > 0; sft >>= 1) {
        if (t < sft) red[t] += red[t + sft];
        __syncthreads();
    }
    int prefix = red[0];

    if (i < N_NODES) g_off[i] = (s[t] - v) + prefix;
    if (i == 0)      g_off[N_NODES] = N_EDGES;
}

// ---------------------------------------------------------------------------
// 3) fill CSR; atomicSub returns g_cnt to exactly 0 (invariant for next call)
// ---------------------------------------------------------------------------
__global__ void __launch_bounds__(256) fill_kernel(
    const int* __restrict__ src, const int* __restrict__ dst)
{
    int e = blockIdx.x * blockDim.x + threadIdx.x;
    if (e >= N_EDGES) return;
    int d = __ldg(&dst[e]);
    int p = atomicSub(&g_cnt[d], 1) - 1;
    g_sadj[g_off[d] + p] = __ldg(&src[e]);
}

// ---------------------------------------------------------------------------
// 4) GEMM: A = x [50000x128] fp32 (split fp16 hi/lo), B^T = [Ws | Wn] (N=256).
//    N-chunked (4 x 64 cols): chunks 0-1 -> out = x@Ws + b (fp32),
//    chunks 2-3 -> g_y = fp16(x@Wn).  smem 104 KB -> 2 blocks/SM.
// ---------------------------------------------------------------------------
#define A_STRIDE 136
#define B_STRIDE 136
#define SM_A_HI  0
#define SM_A_LO  (M_BLK * A_STRIDE)              // 17408
#define SM_B_HI  (2 * M_BLK * A_STRIDE)          // 34816
#define SM_B_LO  (SM_B_HI + 64 * B_STRIDE)       // 43520
#define SMEM_HALVES (SM_B_HI + 2 * 64 * B_STRIDE)   // 52224
#define SMEM_BYTES  (SMEM_HALVES * 2)               // 104448

__device__ __forceinline__ void ldsm_x4(uint32_t* r, uint32_t addr) {
    asm volatile("ldmatrix.sync.aligned.m8n8.x4.shared.b16 {%0,%1,%2,%3}, [%4];"
                 : "=r"(r[0]), "=r"(r[1]), "=r"(r[2]), "=r"(r[3]) : "r"(addr));
}
__device__ __forceinline__ void mma16816(float* c, const uint32_t* a, const uint32_t* b) {
    asm volatile(
        "mma.sync.aligned.m16n8k16.row.col.f32.f16.f16.f32 "
        "{%0,%1,%2,%3}, {%4,%5,%6,%7}, {%8,%9}, {%0,%1,%2,%3};"
        : "+f"(c[0]), "+f"(c[1]), "+f"(c[2]), "+f"(c[3])
        : "r"(a[0]), "r"(a[1]), "r"(a[2]), "r"(a[3]), "r"(b[0]), "r"(b[1]));
}

__global__ void __launch_bounds__(128) gemm_kernel(
    const float* __restrict__ x,
    const float* __restrict__ b,
    float*       __restrict__ out)
{
    extern __shared__ __half sm[];
    __half* A_hi = sm + SM_A_HI;
    __half* A_lo = sm + SM_A_LO;
    __half* B_hi = sm + SM_B_HI;
    __half* B_lo = sm + SM_B_LO;

    const int t    = threadIdx.x;
    const int warp = t >> 5;
    const int lane = t & 31;
    const int base = blockIdx.x * M_BLK;

    // ---- stage A once: 128 rows of x, fp32 -> fp16 hi/lo ----
    {
        int row_off = t >> 5;          // 0..3
        int l16     = t & 31;          // float4 index (k = 4*l16)
        #pragma unroll 8
        for (int it = 0; it < 32; it++) {
            int row  = it * 4 + row_off;
            int node = base + row;
            float4 v = make_float4(0.f, 0.f, 0.f, 0.f);
            if (node < N_NODES)
                v = reinterpret_cast<const float4*>(x + (size_t)node * D)[l16];
            __half h0 = __float2half_rn(v.x), h1 = __float2half_rn(v.y);
            __half h2 = __float2half_rn(v.z), h3 = __float2half_rn(v.w);
            __half l0 = __float2half_rn(v.x - __half2float(h0));
            __half l1 = __float2half_rn(v.y - __half2float(h1));
            __half l2 = __float2half_rn(v.z - __half2float(h2));
            __half l3 = __float2half_rn(v.w - __half2float(h3));
            int off = row * A_STRIDE + l16 * 4;
            __half2 ph0 = __halves2half2(h0, h1), ph1 = __halves2half2(h2, h3);
            __half2 pl0 = __halves2half2(l0, l1), pl1 = __halves2half2(l2, l3);
            uint2 uh, ul;
            uh.x = *reinterpret_cast<uint32_t*>(&ph0);
            uh.y = *reinterpret_cast<uint32_t*>(&ph1);
            ul.x = *reinterpret_cast<uint32_t*>(&pl0);
            ul.y = *reinterpret_cast<uint32_t*>(&pl1);
            *reinterpret_cast<uint2*>(A_hi + off) = uh;
            *reinterpret_cast<uint2*>(A_lo + off) = ul;
        }
    }

    const int mrow = warp * 32;
    const int a_r  = lane & 15;
    const int a_k  = (lane >> 4) * 8;
    const int b_m  = lane >> 3;        // x4 matrix idx 0..3
    const int b_r  = lane & 7;
    const int b_no = (b_m >> 1) * 8;   // n offset 0/8
    const int b_ko = (b_m & 1) * 8;    // k offset 0/8

    for (int nc = 0; nc < 4; nc++) {
        // ---- stage B chunk: 64 output-cols x 128 k, hi+lo ----
        __syncthreads();
        {
            #pragma unroll 8
            for (int idx = t; idx < 64 * 16; idx += 128) {
                int n = idx >> 4, q = idx & 15;       // q: uint4 (8 halves)
                int ng = nc * 64 + n;
                const uint4* sh = reinterpret_cast<const uint4*>(g_Whi + ng * D) + q;
                const uint4* sl = reinterpret_cast<const uint4*>(g_Wlo + ng * D) + q;
                *reinterpret_cast<uint4*>(B_hi + n * B_STRIDE + q * 8) = *sh;
                *reinterpret_cast<uint4*>(B_lo + n * B_STRIDE + q * 8) = *sl;
            }
        }
        __syncthreads();

        float c[2][8][4];
        #pragma unroll
        for (int mt = 0; mt < 2; mt++)
            #pragma unroll
            for (int nt = 0; nt < 8; nt++)
                #pragma unroll
                for (int i = 0; i < 4; i++) c[mt][nt][i] = 0.f;

        #pragma unroll
        for (int kt = 0; kt < 8; kt++) {
            int kk = kt * 16;

            uint32_t ah[2][4], al[2][4];
            #pragma unroll
            for (int mt = 0; mt < 2; mt++) {
                int arow = mrow + mt * 16 + a_r;
                ldsm_x4(ah[mt], (uint32_t)__cvta_generic_to_shared(
                    A_hi + arow * A_STRIDE + kk + a_k));
                ldsm_x4(al[mt], (uint32_t)__cvta_generic_to_shared(
                    A_lo + arow * A_STRIDE + kk + a_k));
            }

            #pragma unroll
            for (int np = 0; np < 4; np++) {          // n-tile pairs (16 cols)
                uint32_t bh4[4], bl4[4];
                int nrow = np * 16 + b_no + b_r;
                ldsm_x4(bh4, (uint32_t)__cvta_generic_to_shared(
                    B_hi + nrow * B_STRIDE + kk + b_ko));
                ldsm_x4(bl4, (uint32_t)__cvta_generic_to_shared(
                    B_lo + nrow * B_STRIDE + kk + b_ko));

                #pragma unroll
                for (int ht = 0; ht < 2; ht++) {
                    int nt = np * 2 + ht;
                    const uint32_t* bh = bh4 + ht * 2;
                    const uint32_t* bl = bl4 + ht * 2;
                    #pragma unroll
                    for (int mt = 0; mt < 2; mt++) {
                        mma16816(c[mt][nt], ah[mt], bh);   // AhBh
                        mma16816(c[mt][nt], al[mt], bh);   // AlBh
                        mma16816(c[mt][nt], ah[mt], bl);   // AhBl
                    }
                }
            }
        }

        // ---- epilogue: chunks 0-1 -> out (+bias); chunks 2-3 -> g_y fp16 ----
        #pragma unroll
        for (int nt = 0; nt < 8; nt++) {
            int ng = nc * 64 + nt * 8 + (lane & 3) * 2;   // global output col
            #pragma unroll
            for (int mt = 0; mt < 2; mt++) {
                int r0 = base + mrow + mt * 16 + (lane >> 2);
                int r1 = r0 + 8;
                if (nc < 2) {
                    float2 bv = *reinterpret_cast<const float2*>(b + ng);
                    if (r0 < N_NODES) {
                        float2 o; o.x = c[mt][nt][0] + bv.x; o.y = c[mt][nt][1] + bv.y;
                        *reinterpret_cast<float2*>(out + (size_t)r0 * D + ng) = o;
                    }
                    if (r1 < N_NODES) {
                        float2 o; o.x = c[mt][nt][2] + bv.x; o.y = c[mt][nt][3] + bv.y;
                        *reinterpret_cast<float2*>(out + (size_t)r1 * D + ng) = o;
                    }
                } else {
                    int col = ng - 128;
                    if (r0 < N_NODES) {
                        __half2 h = __floats2half2_rn(c[mt][nt][0], c[mt][nt][1]);
                        *reinterpret_cast<__half2*>(g_y + (size_t)r0 * D + col) = h;
                    }
                    if (r1 < N_NODES) {
                        __half2 h = __floats2half2_rn(c[mt][nt][2], c[mt][nt][3]);
                        *reinterpret_cast<__half2*>(g_y + (size_t)r1 * D + col) = h;
                    }
                }
            }
        }
    }
}

// ---------------------------------------------------------------------------
// 5) aggregate y over in-edges and RMW-add the mean into out.
//    One warp per node; lane owns 4 halves (uint2 gather); fp32 accumulate.
// ---------------------------------------------------------------------------
__global__ void __launch_bounds__(256) agg_kernel(float* __restrict__ out) {
    int v    = (blockIdx.x * blockDim.x + threadIdx.x) >> 5;
    int lane = threadIdx.x & 31;
    if (v >= N_NODES) return;

    int beg = g_off[v];
    int end = g_off[v + 1];

    float4 acc = make_float4(0.f, 0.f, 0.f, 0.f);

    int i = beg;
    for (; i + 1 < end; i += 2) {
        int s0 = g_sadj[i];
        int s1 = g_sadj[i + 1];
        uint2 p0 = reinterpret_cast<const uint2*>(g_y + (size_t)s0 * D)[lane];
        uint2 p1 = reinterpret_cast<const uint2*>(g_y + (size_t)s1 * D)[lane];
        float2 a = __half22float2(*reinterpret_cast<const __half2*>(&p0.x));
        float2 b = __half22float2(*reinterpret_cast<const __half2*>(&p0.y));
        float2 c = __half22float2(*reinterpret_cast<const __half2*>(&p1.x));
        float2 d = __half22float2(*reinterpret_cast<const __half2*>(&p1.y));
        acc.x += a.x + c.x; acc.y += a.y + c.y;
        acc.z += b.x + d.x; acc.w += b.y + d.y;
    }
    if (i < end) {
        int s0 = g_sadj[i];
        uint2 p0 = reinterpret_cast<const uint2*>(g_y + (size_t)s0 * D)[lane];
        float2 a = __half22float2(*reinterpret_cast<const __half2*>(&p0.x));
        float2 b = __half22float2(*reinterpret_cast<const __half2*>(&p0.y));
        acc.x += a.x; acc.y += a.y; acc.z += b.x; acc.w += b.y;
    }

    int deg = end - beg;
    float inv = (deg > 0) ? (1.0f / (float)deg) : 0.0f;
    float4* op = reinterpret_cast<float4*>(out + (size_t)v * D + lane * 4);
    float4 cur = *op;
    cur.x += acc.x * inv; cur.y += acc.y * inv;
    cur.z += acc.z * inv; cur.w += acc.w * inv;
    *op = cur;
}

// ---------------------------------------------------------------------------
// Launch (5 kernels, single stream).
// Inputs: x, src, dst, W_self, W_neigh, b
// ---------------------------------------------------------------------------
extern "C" void kernel_launch(void* const* d_in, const int* in_sizes, int n_in,
                              void* d_out, int out_size)
{
    const float* x   = (const float*)d_in[0];
    const int*   src = (const int*)  d_in[1];
    const int*   dst = (const int*)  d_in[2];
    const float* Ws  = (const float*)d_in[3];
    const float* Wn  = (const float*)d_in[4];
    const float* b   = (const float*)d_in[5];
    float*       out = (float*)d_out;

    static bool attr_set = false;
    if (!attr_set) {
        cudaFuncSetAttribute(gemm_kernel,
                             cudaFuncAttributeMaxDynamicSharedMemorySize, SMEM_BYTES);
        attr_set = true;
    }

    init_hist_kernel<<<EBLK + 128, 256>>>(dst, Ws, Wn);
    scan_kernel<<<NBLK, 256>>>();
    fill_kernel<<<EBLK, 256>>>(src, dst);
    gemm_kernel<<<OUT_BLOCKS, 128, SMEM_BYTES>>>(x, b, out);
    agg_kernel<<<(N_NODES * 32 + 255) / 256, 256>>>(out);
}

// round 12
// speedup vs baseline: 1.2434x; 1.0552x over previous
#include <cuda_runtime.h>
#include <cuda_fp16.h>
#include <cstdint>

#define N_NODES 50000
#define N_EDGES 625000
#define D 128
#define NBLK 196                     // scan blocks (50000/256)
#define EBLK 2442                    // edge blocks (625000/256)
#define M_BLK 128
#define OUT_BLOCKS 391               // ceil(50000/128)
#define SCAN_READY 0x40000000

// ---------------------------------------------------------------------------
// Device scratch. g_cnt invariant: starts 0 (module load), hist adds, fill
// subtracts back to exactly 0 -> no zeroing kernel needed, deterministic.
// ---------------------------------------------------------------------------
__device__ int    g_cnt[N_NODES];
__device__ int    g_state[NBLK];         // lookback scan: aggregate | READY
__device__ int    g_off[N_NODES + 1];    // CSR row offsets
__device__ int    g_sadj[N_EDGES];       // CSR: src node per in-edge slot
__device__ __half g_y[N_NODES * D];      // y = x @ Wn, fp16 (gathered by agg)
__device__ __half g_Whi[256 * D];        // B^T [n][k]: n<128 Ws^T, n>=128 Wn^T (hi)
__device__ __half g_Wlo[256 * D];        // (lo)

// ---------------------------------------------------------------------------
// 1) fused init: blocks [0,EBLK) histogram dst into g_cnt;
//    blocks [EBLK, EBLK+128): W -> [n][k] fp16 hi/lo split (+ g_state clear)
// ---------------------------------------------------------------------------
__global__ void __launch_bounds__(256) init_hist_kernel(
    const int* __restrict__ dst,
    const float* __restrict__ Ws, const float* __restrict__ Wn)
{
    int bid = blockIdx.x, t = threadIdx.x;
    if (bid < EBLK) {
        int e = bid * 256 + t;
        if (e < N_EDGES) atomicAdd(&g_cnt[dst[e]], 1);
    } else {
        int wb = bid - EBLK;                 // 0..127
        if (wb == 0 && t < NBLK) g_state[t] = 0;
        int n = wb * 2 + (t >> 7);           // 0..255 (output col: Ws then Wn)
        int k = t & 127;                     // 0..127 (input dim)
        float w = (n < D) ? Ws[k * D + n] : Wn[k * D + (n - D)];
        __half hi = __float2half_rn(w);
        __half lo = __float2half_rn(w - __half2float(hi));
        g_Whi[n * D + k] = hi;
        g_Wlo[n * D + k] = lo;
    }
}

// ---------------------------------------------------------------------------
// 2) single-pass scan, aggregate-only decoupled lookback (g_cnt -> g_off).
// ---------------------------------------------------------------------------
__global__ void __launch_bounds__(256) scan_kernel() {
    __shared__ int s[256];
    __shared__ int red[256];
    int t = threadIdx.x, bid = blockIdx.x;
    int i = bid * 256 + t;

    int v = (i < N_NODES) ? g_cnt[i] : 0;
    s[t] = v; __syncthreads();
    #pragma unroll
    for (int d = 1; d < 256; d <<= 1) {
        int add = (t >= d) ? s[t - d] : 0;
        __syncthreads();
        s[t] += add; __syncthreads();
    }
    if (t == 0) atomicExch(&g_state[bid], s[255] | SCAN_READY);

    int pref = 0;
    if (t < bid) {
        int st;
        do { st = atomicAdd(&g_state[t], 0); } while (!(st & SCAN_READY));
        pref = st & (SCAN_READY - 1);
    }
    red[t] = pref; __syncthreads();
    #pragma unroll
    for (int sft = 128; sft > 0; sft >>= 1) {
        if (t < sft) red[t] += red[t + sft];
        __syncthreads();
    }
    int prefix = red[0];

    if (i < N_NODES) g_off[i] = (s[t] - v) + prefix;
    if (i == 0)      g_off[N_NODES] = N_EDGES;
}

// ---------------------------------------------------------------------------
// 3) fill CSR; atomicSub returns g_cnt to exactly 0
// ---------------------------------------------------------------------------
__global__ void __launch_bounds__(256) fill_kernel(
    const int* __restrict__ src, const int* __restrict__ dst)
{
    int e = blockIdx.x * blockDim.x + threadIdx.x;
    if (e >= N_EDGES) return;
    int d = __ldg(&dst[e]);
    int p = atomicSub(&g_cnt[d], 1) - 1;
    g_sadj[g_off[d] + p] = __ldg(&src[e]);
}

// ---------------------------------------------------------------------------
// 4) GEMM: A = x [50000x128] fp32 (split fp16 hi/lo), B^T = [Ws | Wn] (N=256).
//    256 threads / 8 warps, each warp owns 16 rows (1 m-tile) -> ~80 regs,
//    2 blocks/SM, 16 warps/SM resident (was 128 regs / 7 warps / 10.6% occ).
//    N-chunked (4 x 64 cols): chunks 0-1 -> out = x@Ws + b (fp32),
//    chunks 2-3 -> g_y = fp16(x@Wn).
// ---------------------------------------------------------------------------
#define GEMM_THREADS 256
#define A_STRIDE 136
#define B_STRIDE 136
#define SM_A_HI  0
#define SM_A_LO  (M_BLK * A_STRIDE)              // 17408
#define SM_B_HI  (2 * M_BLK * A_STRIDE)          // 34816
#define SM_B_LO  (SM_B_HI + 64 * B_STRIDE)       // 43520
#define SMEM_HALVES (SM_B_HI + 2 * 64 * B_STRIDE)   // 52224
#define SMEM_BYTES  (SMEM_HALVES * 2)               // 104448

__device__ __forceinline__ void ldsm_x4(uint32_t* r, uint32_t addr) {
    asm volatile("ldmatrix.sync.aligned.m8n8.x4.shared.b16 {%0,%1,%2,%3}, [%4];"
                 : "=r"(r[0]), "=r"(r[1]), "=r"(r[2]), "=r"(r[3]) : "r"(addr));
}
__device__ __forceinline__ void mma16816(float* c, const uint32_t* a, const uint32_t* b) {
    asm volatile(
        "mma.sync.aligned.m16n8k16.row.col.f32.f16.f16.f32 "
        "{%0,%1,%2,%3}, {%4,%5,%6,%7}, {%8,%9}, {%0,%1,%2,%3};"
        : "+f"(c[0]), "+f"(c[1]), "+f"(c[2]), "+f"(c[3])
        : "r"(a[0]), "r"(a[1]), "r"(a[2]), "r"(a[3]), "r"(b[0]), "r"(b[1]));
}

__global__ void __launch_bounds__(GEMM_THREADS) gemm_kernel(
    const float* __restrict__ x,
    const float* __restrict__ b,
    float*       __restrict__ out)
{
    extern __shared__ __half sm[];
    __half* A_hi = sm + SM_A_HI;
    __half* A_lo = sm + SM_A_LO;
    __half* B_hi = sm + SM_B_HI;
    __half* B_lo = sm + SM_B_LO;

    const int t    = threadIdx.x;
    const int warp = t >> 5;           // 0..7, warp owns rows [16*warp, 16*warp+16)
    const int lane = t & 31;
    const int base = blockIdx.x * M_BLK;

    // ---- stage A once: 128 rows of x, fp32 -> fp16 hi/lo (256 threads) ----
    {
        int row_off = t >> 5;          // 0..7
        int l16     = t & 31;          // float4 index (k = 4*l16)
        #pragma unroll 4
        for (int it = 0; it < 16; it++) {
            int row  = it * 8 + row_off;
            int node = base + row;
            float4 v = make_float4(0.f, 0.f, 0.f, 0.f);
            if (node < N_NODES)
                v = reinterpret_cast<const float4*>(x + (size_t)node * D)[l16];
            __half h0 = __float2half_rn(v.x), h1 = __float2half_rn(v.y);
            __half h2 = __float2half_rn(v.z), h3 = __float2half_rn(v.w);
            __half l0 = __float2half_rn(v.x - __half2float(h0));
            __half l1 = __float2half_rn(v.y - __half2float(h1));
            __half l2 = __float2half_rn(v.z - __half2float(h2));
            __half l3 = __float2half_rn(v.w - __half2float(h3));
            int off = row * A_STRIDE + l16 * 4;
            __half2 ph0 = __halves2half2(h0, h1), ph1 = __halves2half2(h2, h3);
            __half2 pl0 = __halves2half2(l0, l1), pl1 = __halves2half2(l2, l3);
            uint2 uh, ul;
            uh.x = *reinterpret_cast<uint32_t*>(&ph0);
            uh.y = *reinterpret_cast<uint32_t*>(&ph1);
            ul.x = *reinterpret_cast<uint32_t*>(&pl0);
            ul.y = *reinterpret_cast<uint32_t*>(&pl1);
            *reinterpret_cast<uint2*>(A_hi + off) = uh;
            *reinterpret_cast<uint2*>(A_lo + off) = ul;
        }
    }

    const int mrow = warp * 16;        // this warp's 16-row tile
    const int a_r  = lane & 15;
    const int a_k  = (lane >> 4) * 8;
    const int b_m  = lane >> 3;        // x4 matrix idx 0..3
    const int b_r  = lane & 7;
    const int b_no = (b_m >> 1) * 8;   // n offset 0/8
    const int b_ko = (b_m & 1) * 8;    // k offset 0/8

    for (int nc = 0; nc < 4; nc++) {
        // ---- stage B chunk: 64 output-cols x 128 k, hi+lo (256 threads) ----
        __syncthreads();
        {
            #pragma unroll 4
            for (int idx = t; idx < 64 * 16; idx += GEMM_THREADS) {
                int n = idx >> 4, q = idx & 15;       // q: uint4 (8 halves)
                int ng = nc * 64 + n;
                const uint4* sh = reinterpret_cast<const uint4*>(g_Whi + ng * D) + q;
                const uint4* sl = reinterpret_cast<const uint4*>(g_Wlo + ng * D) + q;
                *reinterpret_cast<uint4*>(B_hi + n * B_STRIDE + q * 8) = *sh;
                *reinterpret_cast<uint4*>(B_lo + n * B_STRIDE + q * 8) = *sl;
            }
        }
        __syncthreads();

        float c[8][4];
        #pragma unroll
        for (int nt = 0; nt < 8; nt++)
            #pragma unroll
            for (int i = 0; i < 4; i++) c[nt][i] = 0.f;

        #pragma unroll
        for (int kt = 0; kt < 8; kt++) {
            int kk = kt * 16;

            uint32_t ah[4], al[4];
            {
                int arow = mrow + a_r;
                ldsm_x4(ah, (uint32_t)__cvta_generic_to_shared(
                    A_hi + arow * A_STRIDE + kk + a_k));
                ldsm_x4(al, (uint32_t)__cvta_generic_to_shared(
                    A_lo + arow * A_STRIDE + kk + a_k));
            }

            #pragma unroll
            for (int np = 0; np < 4; np++) {          // n-tile pairs (16 cols)
                uint32_t bh4[4], bl4[4];
                int nrow = np * 16 + b_no + b_r;
                ldsm_x4(bh4, (uint32_t)__cvta_generic_to_shared(
                    B_hi + nrow * B_STRIDE + kk + b_ko));
                ldsm_x4(bl4, (uint32_t)__cvta_generic_to_shared(
                    B_lo + nrow * B_STRIDE + kk + b_ko));

                #pragma unroll
                for (int ht = 0; ht < 2; ht++) {
                    int nt = np * 2 + ht;
                    const uint32_t* bh = bh4 + ht * 2;
                    const uint32_t* bl = bl4 + ht * 2;
                    mma16816(c[nt], ah, bh);   // AhBh
                    mma16816(c[nt], al, bh);   // AlBh
                    mma16816(c[nt], ah, bl);   // AhBl
                }
            }
        }

        // ---- epilogue: chunks 0-1 -> out (+bias); chunks 2-3 -> g_y fp16 ----
        #pragma unroll
        for (int nt = 0; nt < 8; nt++) {
            int ng = nc * 64 + nt * 8 + (lane & 3) * 2;   // global output col
            int r0 = base + mrow + (lane >> 2);
            int r1 = r0 + 8;
            if (nc < 2) {
                float2 bv = *reinterpret_cast<const float2*>(b + ng);
                if (r0 < N_NODES) {
                    float2 o; o.x = c[nt][0] + bv.x; o.y = c[nt][1] + bv.y;
                    *reinterpret_cast<float2*>(out + (size_t)r0 * D + ng) = o;
                }
                if (r1 < N_NODES) {
                    float2 o; o.x = c[nt][2] + bv.x; o.y = c[nt][3] + bv.y;
                    *reinterpret_cast<float2*>(out + (size_t)r1 * D + ng) = o;
                }
            } else {
                int col = ng - 128;
                if (r0 < N_NODES) {
                    __half2 h = __floats2half2_rn(c[nt][0], c[nt][1]);
                    *reinterpret_cast<__half2*>(g_y + (size_t)r0 * D + col) = h;
                }
                if (r1 < N_NODES) {
                    __half2 h = __floats2half2_rn(c[nt][2], c[nt][3]);
                    *reinterpret_cast<__half2*>(g_y + (size_t)r1 * D + col) = h;
                }
            }
        }
    }
}

// ---------------------------------------------------------------------------
// 5) aggregate y over in-edges and RMW-add the mean into out.
//    One warp per node; lane owns 4 halves (uint2 gather); fp32 accumulate.
// ---------------------------------------------------------------------------
__global__ void __launch_bounds__(256) agg_kernel(float* __restrict__ out) {
    int v    = (blockIdx.x * blockDim.x + threadIdx.x) >> 5;
    int lane = threadIdx.x & 31;
    if (v >= N_NODES) return;

    int beg = g_off[v];
    int end = g_off[v + 1];

    float4 acc = make_float4(0.f, 0.f, 0.f, 0.f);

    int i = beg;
    for (; i + 1 < end; i += 2) {
        int s0 = g_sadj[i];
        int s1 = g_sadj[i + 1];
        uint2 p0 = reinterpret_cast<const uint2*>(g_y + (size_t)s0 * D)[lane];
        uint2 p1 = reinterpret_cast<const uint2*>(g_y + (size_t)s1 * D)[lane];
        float2 a = __half22float2(*reinterpret_cast<const __half2*>(&p0.x));
        float2 b = __half22float2(*reinterpret_cast<const __half2*>(&p0.y));
        float2 c = __half22float2(*reinterpret_cast<const __half2*>(&p1.x));
        float2 d = __half22float2(*reinterpret_cast<const __half2*>(&p1.y));
        acc.x += a.x + c.x; acc.y += a.y + c.y;
        acc.z += b.x + d.x; acc.w += b.y + d.y;
    }
    if (i < end) {
        int s0 = g_sadj[i];
        uint2 p0 = reinterpret_cast<const uint2*>(g_y + (size_t)s0 * D)[lane];
        float2 a = __half22float2(*reinterpret_cast<const __half2*>(&p0.x));
        float2 b = __half22float2(*reinterpret_cast<const __half2*>(&p0.y));
        acc.x += a.x; acc.y += a.y; acc.z += b.x; acc.w += b.y;
    }

    int deg = end - beg;
    float inv = (deg > 0) ? (1.0f / (float)deg) : 0.0f;
    float4* op = reinterpret_cast<float4*>(out + (size_t)v * D + lane * 4);
    float4 cur = *op;
    cur.x += acc.x * inv; cur.y += acc.y * inv;
    cur.z += acc.z * inv; cur.w += acc.w * inv;
    *op = cur;
}

// ---------------------------------------------------------------------------
// Launch (5 kernels, single stream).
// Inputs: x, src, dst, W_self, W_neigh, b
// ---------------------------------------------------------------------------
extern "C" void kernel_launch(void* const* d_in, const int* in_sizes, int n_in,
                              void* d_out, int out_size)
{
    const float* x   = (const float*)d_in[0];
    const int*   src = (const int*)  d_in[1];
    const int*   dst = (const int*)  d_in[2];
    const float* Ws  = (const float*)d_in[3];
    const float* Wn  = (const float*)d_in[4];
    const float* b   = (const float*)d_in[5];
    float*       out = (float*)d_out;

    static bool attr_set = false;
    if (!attr_set) {
        cudaFuncSetAttribute(gemm_kernel,
                             cudaFuncAttributeMaxDynamicSharedMemorySize, SMEM_BYTES);
        attr_set = true;
    }

    init_hist_kernel<<<EBLK + 128, 256>>>(dst, Ws, Wn);
    scan_kernel<<<NBLK, 256>>>();
    fill_kernel<<<EBLK, 256>>>(src, dst);
    gemm_kernel<<<OUT_BLOCKS, GEMM_THREADS, SMEM_BYTES>>>(x, b, out);
    agg_kernel<<<(N_NODES * 32 + 255) / 256, 256>>>(out);
}

// round 13
// speedup vs baseline: 1.5935x; 1.2816x over previous
#include <cuda_runtime.h>
#include <cuda_fp16.h>
#include <cstdint>

#define N_NODES 50000
#define N_EDGES 625000
#define D 128
#define NBLK 196                     // scan blocks (50000/256)
#define EBLK 2442                    // edge blocks (625000/256)
#define M_BLK 128
#define OUT_BLOCKS 391               // ceil(50000/128)
#define SCAN_READY 0x40000000

// ---------------------------------------------------------------------------
// Device scratch. g_cnt invariant: starts 0 (module load), hist adds, fill
// subtracts back to exactly 0 -> no zeroing kernel needed, deterministic.
// ---------------------------------------------------------------------------
__device__ int    g_cnt[N_NODES];
__device__ int    g_state[NBLK];         // lookback scan: aggregate | READY
__device__ int    g_off[N_NODES + 1];    // CSR row offsets
__device__ int    g_sadj[N_EDGES];       // CSR: src node per in-edge slot
__device__ __half g_y[N_NODES * D];      // y = x @ Wn, fp16 (gathered by agg)
__device__ __half g_Wh[256 * D];         // B^T [n][k]: n<128 Ws^T, n>=128 Wn^T

// ---------------------------------------------------------------------------
// 1) fused init: blocks [0,EBLK) histogram dst into g_cnt;
//    blocks [EBLK, EBLK+128): W -> [n][k] fp16 (+ g_state clear)
// ---------------------------------------------------------------------------
__global__ void __launch_bounds__(256) init_hist_kernel(
    const int* __restrict__ dst,
    const float* __restrict__ Ws, const float* __restrict__ Wn)
{
    int bid = blockIdx.x, t = threadIdx.x;
    if (bid < EBLK) {
        int e = bid * 256 + t;
        if (e < N_EDGES) atomicAdd(&g_cnt[dst[e]], 1);
    } else {
        int wb = bid - EBLK;                 // 0..127
        if (wb == 0 && t < NBLK) g_state[t] = 0;
        int n = wb * 2 + (t >> 7);           // 0..255 (output col: Ws then Wn)
        int k = t & 127;                     // 0..127 (input dim)
        float w = (n < D) ? Ws[k * D + n] : Wn[k * D + (n - D)];
        g_Wh[n * D + k] = __float2half_rn(w);
    }
}

// ---------------------------------------------------------------------------
// 2) single-pass scan, aggregate-only decoupled lookback (g_cnt -> g_off).
// ---------------------------------------------------------------------------
__global__ void __launch_bounds__(256) scan_kernel() {
    __shared__ int s[256];
    __shared__ int red[256];
    int t = threadIdx.x, bid = blockIdx.x;
    int i = bid * 256 + t;

    int v = (i < N_NODES) ? g_cnt[i] : 0;
    s[t] = v; __syncthreads();
    #pragma unroll
    for (int d = 1; d < 256; d <<= 1) {
        int add = (t >= d) ? s[t - d] : 0;
        __syncthreads();
        s[t] += add; __syncthreads();
    }
    if (t == 0) atomicExch(&g_state[bid], s[255] | SCAN_READY);

    int pref = 0;
    if (t < bid) {
        int st;
        do { st = atomicAdd(&g_state[t], 0); } while (!(st & SCAN_READY));
        pref = st & (SCAN_READY - 1);
    }
    red[t] = pref; __syncthreads();
    #pragma unroll
    for (int sft = 128; sft > 0; sft >>= 1) {
        if (t < sft) red[t] += red[t + sft];
        __syncthreads();
    }
    int prefix = red[0];

    if (i < N_NODES) g_off[i] = (s[t] - v) + prefix;
    if (i == 0)      g_off[N_NODES] = N_EDGES;
}

// ---------------------------------------------------------------------------
// 3) fill CSR; atomicSub returns g_cnt to exactly 0
// ---------------------------------------------------------------------------
__global__ void __launch_bounds__(256) fill_kernel(
    const int* __restrict__ src, const int* __restrict__ dst)
{
    int e = blockIdx.x * blockDim.x + threadIdx.x;
    if (e >= N_EDGES) return;
    int d = __ldg(&dst[e]);
    int p = atomicSub(&g_cnt[d], 1) - 1;
    g_sadj[g_off[d] + p] = __ldg(&src[e]);
}

// ---------------------------------------------------------------------------
// 4) GEMM: A = x [50000x128] fp16, B^T = [Ws | Wn] fp16 (N=256), single-term.
//    256 threads / 8 warps, warp owns 16 rows. smem ~51 KB -> 3-4 blocks/SM
//    -> grid 391 fits in ONE wave (no tail quantization).
//    N-chunked (4 x 64 cols): chunks 0-1 -> out = x@Ws + b (fp32),
//    chunks 2-3 -> g_y = fp16(x@Wn).
// ---------------------------------------------------------------------------
#define GEMM_THREADS 256
#define A_STRIDE 136
#define B_STRIDE 136
#define SM_A    0
#define SM_B    (M_BLK * A_STRIDE)                  // 17408
#define SMEM_HALVES (M_BLK * A_STRIDE + 64 * B_STRIDE)  // 26112
#define SMEM_BYTES  (SMEM_HALVES * 2)                   // 52224

__device__ __forceinline__ void ldsm_x4(uint32_t* r, uint32_t addr) {
    asm volatile("ldmatrix.sync.aligned.m8n8.x4.shared.b16 {%0,%1,%2,%3}, [%4];"
                 : "=r"(r[0]), "=r"(r[1]), "=r"(r[2]), "=r"(r[3]) : "r"(addr));
}
__device__ __forceinline__ void mma16816(float* c, const uint32_t* a, const uint32_t* b) {
    asm volatile(
        "mma.sync.aligned.m16n8k16.row.col.f32.f16.f16.f32 "
        "{%0,%1,%2,%3}, {%4,%5,%6,%7}, {%8,%9}, {%0,%1,%2,%3};"
        : "+f"(c[0]), "+f"(c[1]), "+f"(c[2]), "+f"(c[3])
        : "r"(a[0]), "r"(a[1]), "r"(a[2]), "r"(a[3]), "r"(b[0]), "r"(b[1]));
}

__global__ void __launch_bounds__(GEMM_THREADS) gemm_kernel(
    const float* __restrict__ x,
    const float* __restrict__ b,
    float*       __restrict__ out)
{
    extern __shared__ __half sm[];
    __half* A_h = sm + SM_A;
    __half* B_h = sm + SM_B;

    const int t    = threadIdx.x;
    const int warp = t >> 5;           // 0..7, warp owns rows [16*warp, +16)
    const int lane = t & 31;
    const int base = blockIdx.x * M_BLK;

    // ---- stage A once: 128 rows of x, fp32 -> fp16 (256 threads) ----
    {
        int row_off = t >> 5;          // 0..7
        int l16     = t & 31;          // float4 index (k = 4*l16)
        #pragma unroll 4
        for (int it = 0; it < 16; it++) {
            int row  = it * 8 + row_off;
            int node = base + row;
            float4 v = make_float4(0.f, 0.f, 0.f, 0.f);
            if (node < N_NODES)
                v = reinterpret_cast<const float4*>(x + (size_t)node * D)[l16];
            __half2 p0 = __floats2half2_rn(v.x, v.y);
            __half2 p1 = __floats2half2_rn(v.z, v.w);
            uint2 u;
            u.x = *reinterpret_cast<uint32_t*>(&p0);
            u.y = *reinterpret_cast<uint32_t*>(&p1);
            *reinterpret_cast<uint2*>(A_h + row * A_STRIDE + l16 * 4) = u;
        }
    }

    const int mrow = warp * 16;
    const int a_r  = lane & 15;
    const int a_k  = (lane >> 4) * 8;
    const int b_m  = lane >> 3;        // x4 matrix idx 0..3
    const int b_r  = lane & 7;
    const int b_no = (b_m >> 1) * 8;   // n offset 0/8
    const int b_ko = (b_m & 1) * 8;    // k offset 0/8

    for (int nc = 0; nc < 4; nc++) {
        // ---- stage B chunk: 64 output-cols x 128 k (256 threads) ----
        __syncthreads();
        {
            #pragma unroll 2
            for (int idx = t; idx < 64 * 16; idx += GEMM_THREADS) {
                int n = idx >> 4, q = idx & 15;       // q: uint4 (8 halves)
                int ng = nc * 64 + n;
                const uint4* sh = reinterpret_cast<const uint4*>(g_Wh + ng * D) + q;
                *reinterpret_cast<uint4*>(B_h + n * B_STRIDE + q * 8) = *sh;
            }
        }
        __syncthreads();

        float c[8][4];
        #pragma unroll
        for (int nt = 0; nt < 8; nt++)
            #pragma unroll
            for (int i = 0; i < 4; i++) c[nt][i] = 0.f;

        #pragma unroll
        for (int kt = 0; kt < 8; kt++) {
            int kk = kt * 16;

            uint32_t a4[4];
            ldsm_x4(a4, (uint32_t)__cvta_generic_to_shared(
                A_h + (mrow + a_r) * A_STRIDE + kk + a_k));

            #pragma unroll
            for (int np = 0; np < 4; np++) {          // n-tile pairs (16 cols)
                uint32_t b4[4];
                int nrow = np * 16 + b_no + b_r;
                ldsm_x4(b4, (uint32_t)__cvta_generic_to_shared(
                    B_h + nrow * B_STRIDE + kk + b_ko));
                mma16816(c[np * 2 + 0], a4, b4 + 0);
                mma16816(c[np * 2 + 1], a4, b4 + 2);
            }
        }

        // ---- epilogue: chunks 0-1 -> out (+bias); chunks 2-3 -> g_y fp16 ----
        #pragma unroll
        for (int nt = 0; nt < 8; nt++) {
            int ng = nc * 64 + nt * 8 + (lane & 3) * 2;   // global output col
            int r0 = base + mrow + (lane >> 2);
            int r1 = r0 + 8;
            if (nc < 2) {
                float2 bv = *reinterpret_cast<const float2*>(b + ng);
                if (r0 < N_NODES) {
                    float2 o; o.x = c[nt][0] + bv.x; o.y = c[nt][1] + bv.y;
                    *reinterpret_cast<float2*>(out + (size_t)r0 * D + ng) = o;
                }
                if (r1 < N_NODES) {
                    float2 o; o.x = c[nt][2] + bv.x; o.y = c[nt][3] + bv.y;
                    *reinterpret_cast<float2*>(out + (size_t)r1 * D + ng) = o;
                }
            } else {
                int col = ng - 128;
                if (r0 < N_NODES) {
                    __half2 h = __floats2half2_rn(c[nt][0], c[nt][1]);
                    *reinterpret_cast<__half2*>(g_y + (size_t)r0 * D + col) = h;
                }
                if (r1 < N_NODES) {
                    __half2 h = __floats2half2_rn(c[nt][2], c[nt][3]);
                    *reinterpret_cast<__half2*>(g_y + (size_t)r1 * D + col) = h;
                }
            }
        }
    }
}

// ---------------------------------------------------------------------------
// 5) aggregate y over in-edges and RMW-add the mean into out.
//    One warp per node; lane owns 4 halves (uint2 gather); fp32 accumulate.
// ---------------------------------------------------------------------------
__global__ void __launch_bounds__(256) agg_kernel(float* __restrict__ out) {
    int v    = (blockIdx.x * blockDim.x + threadIdx.x) >> 5;
    int lane = threadIdx.x & 31;
    if (v >= N_NODES) return;

    int beg = g_off[v];
    int end = g_off[v + 1];

    float4 acc = make_float4(0.f, 0.f, 0.f, 0.f);

    int i = beg;
    for (; i + 1 < end; i += 2) {
        int s0 = g_sadj[i];
        int s1 = g_sadj[i + 1];
        uint2 p0 = reinterpret_cast<const uint2*>(g_y + (size_t)s0 * D)[lane];
        uint2 p1 = reinterpret_cast<const uint2*>(g_y + (size_t)s1 * D)[lane];
        float2 a = __half22float2(*reinterpret_cast<const __half2*>(&p0.x));
        float2 b = __half22float2(*reinterpret_cast<const __half2*>(&p0.y));
        float2 c = __half22float2(*reinterpret_cast<const __half2*>(&p1.x));
        float2 d = __half22float2(*reinterpret_cast<const __half2*>(&p1.y));
        acc.x += a.x + c.x; acc.y += a.y + c.y;
        acc.z += b.x + d.x; acc.w += b.y + d.y;
    }
    if (i < end) {
        int s0 = g_sadj[i];
        uint2 p0 = reinterpret_cast<const uint2*>(g_y + (size_t)s0 * D)[lane];
        float2 a = __half22float2(*reinterpret_cast<const __half2*>(&p0.x));
        float2 b = __half22float2(*reinterpret_cast<const __half2*>(&p0.y));
        acc.x += a.x; acc.y += a.y; acc.z += b.x; acc.w += b.y;
    }

    int deg = end - beg;
    float inv = (deg > 0) ? (1.0f / (float)deg) : 0.0f;
    float4* op = reinterpret_cast<float4*>(out + (size_t)v * D + lane * 4);
    float4 cur = *op;
    cur.x += acc.x * inv; cur.y += acc.y * inv;
    cur.z += acc.z * inv; cur.w += acc.w * inv;
    *op = cur;
}

// ---------------------------------------------------------------------------
// Launch (5 kernels, single stream).
// Inputs: x, src, dst, W_self, W_neigh, b
// ---------------------------------------------------------------------------
extern "C" void kernel_launch(void* const* d_in, const int* in_sizes, int n_in,
                              void* d_out, int out_size)
{
    const float* x   = (const float*)d_in[0];
    const int*   src = (const int*)  d_in[1];
    const int*   dst = (const int*)  d_in[2];
    const float* Ws  = (const float*)d_in[3];
    const float* Wn  = (const float*)d_in[4];
    const float* b   = (const float*)d_in[5];
    float*       out = (float*)d_out;

    static bool attr_set = false;
    if (!attr_set) {
        cudaFuncSetAttribute(gemm_kernel,
                             cudaFuncAttributeMaxDynamicSharedMemorySize, SMEM_BYTES);
        attr_set = true;
    }

    init_hist_kernel<<<EBLK + 128, 256>>>(dst, Ws, Wn);
    scan_kernel<<<NBLK, 256>>>();
    fill_kernel<<<EBLK, 256>>>(src, dst);
    gemm_kernel<<<OUT_BLOCKS, GEMM_THREADS, SMEM_BYTES>>>(x, b, out);
    agg_kernel<<<(N_NODES * 32 + 255) / 256, 256>>>(out);
}